// round 12
// baseline (speedup 1.0000x reference)
#include <cuda_runtime.h>
#include <math.h>

#define NN 100000
#define EE 1600000
#define ET (EE + NN)
#define NB_SCAN ((NN + 1023) / 1024)   // 98

// ---------------- scratch (static device globals; no allocation) ----------------
__device__ int   g_deg[NN];
__device__ int   g_fill[NN];
__device__ int   g_rowptr[NN + 1];
__device__ int   g_csrsrc[ET];
__device__ int   g_bsum[128];
__device__ int   g_total;
__device__ float g_h1[NN * 128];
__device__ float g_as1[NN * 8];
__device__ float g_ad1[NN * 8];
__device__ float g_act1[NN * 128];
__device__ float g_h2[NN * 16];
__device__ float g_as2[NN];
__device__ float g_ad2[NN];

// ---------------- f32x2 helpers ----------------
__device__ __forceinline__ void ffma2(unsigned long long& d, unsigned long long a,
                                      unsigned long long b) {
    asm("fma.rn.f32x2 %0, %1, %2, %0;" : "+l"(d) : "l"(a), "l"(b));
}
__device__ __forceinline__ unsigned long long pack2(float lo, float hi) {
    unsigned long long r;
    asm("mov.b64 %0, {%1, %2};" : "=l"(r) : "f"(lo), "f"(hi));
    return r;
}
__device__ __forceinline__ void unpack2(unsigned long long v, float& lo, float& hi) {
    asm("mov.b64 {%0, %1}, %2;" : "=f"(lo), "=f"(hi) : "l"(v));
}

// ---------------- CSR build ----------------
__global__ void zero_k() {
    int i = blockIdx.x * blockDim.x + threadIdx.x;
    if (i < NN) { g_deg[i] = 0; g_fill[i] = 0; }
}

__global__ void hist_k(const int* __restrict__ ei) {
    int i = blockIdx.x * blockDim.x + threadIdx.x;
    if (i >= ET) return;
    int t = (i < EE) ? ei[EE + i] : (i - EE);   // self-loop tail
    atomicAdd(&g_deg[t], 1);
}

__global__ void scan1_k() {
    __shared__ int sh[1024];
    int t = threadIdx.x;
    int i = blockIdx.x * 1024 + t;
    int v = (i < NN) ? g_deg[i] : 0;
    sh[t] = v;
    __syncthreads();
    for (int off = 1; off < 1024; off <<= 1) {
        int add = (t >= off) ? sh[t - off] : 0;
        __syncthreads();
        sh[t] += add;
        __syncthreads();
    }
    if (i < NN) g_rowptr[i] = sh[t] - v;        // exclusive within block
    if (t == 1023) g_bsum[blockIdx.x] = sh[1023];
}

__global__ void scan2_k() {
    __shared__ int sh[128];
    int t = threadIdx.x;
    int v = (t < NB_SCAN) ? g_bsum[t] : 0;
    sh[t] = v;
    __syncthreads();
    for (int off = 1; off < 128; off <<= 1) {
        int add = (t >= off) ? sh[t - off] : 0;
        __syncthreads();
        sh[t] += add;
        __syncthreads();
    }
    if (t < NB_SCAN) g_bsum[t] = sh[t] - v;     // exclusive block offsets
    if (t == 127) g_total = sh[127];
}

__global__ void scan3_k() {
    int i = blockIdx.x * 1024 + threadIdx.x;
    if (i < NN) g_rowptr[i] += g_bsum[blockIdx.x];
    if (i == 0) g_rowptr[NN] = g_total;
}

__global__ void scatter_k(const int* __restrict__ ei) {
    int i = blockIdx.x * blockDim.x + threadIdx.x;
    if (i >= ET) return;
    int s, t;
    if (i < EE) { s = ei[i]; t = ei[EE + i]; }
    else        { s = i - EE; t = i - EE; }
    int pos = atomicAdd(&g_fill[t], 1);
    g_csrsrc[g_rowptr[t] + pos] = s;
}

// ---------------- layer 1 GEMM via FFMA2: h1 = x @ W1 (128x128) + fused attn coeffs
// Block tile 128 rows x 128 cols, 256 threads (8 warps).
// Warp w owns cols w*16..w*16+16 (= exactly head w); lane owns rows lane*4..lane*4+3.
// Thread tile 4x16: per k-step, 1 LDS.128 (x, 4 swizzled rows) + 4 LDS.128
// (w broadcast) feed 128 FMAs (64 FFMA2) -> 2x the FMA/LDS of the previous
// version, which ncu showed to be L1/shared-bound (80.3% L1, 45.7% fma).
__global__ __launch_bounds__(256) void gemm1_k(const float* __restrict__ X,
                                               const float* __restrict__ W,
                                               const float* __restrict__ Asrc,
                                               const float* __restrict__ Adst) {
    __shared__ float xs[32][128];   // [k][row^swizzle] 16KB
    __shared__ float ws[32][128];   // [k][col]         16KB
    int tid  = threadIdx.x;         // 256
    int wrp  = tid >> 5;            // 0..7 = head / col group
    int lane = tid & 31;            // rows lane*4 .. lane*4+3
    int rowBase = blockIdx.x * 128;

    unsigned long long acc[4][8];
#pragma unroll
    for (int i = 0; i < 4; i++)
#pragma unroll
        for (int j = 0; j < 8; j++) acc[i][j] = 0ull;

    for (int kb = 0; kb < 128; kb += 32) {
        // fill xs: 128 rows x 32 k = 1024 float4 loads, 4 per thread (coalesced),
        // scattered as 4 swizzled STS.32 each (conflict-free: r low bits ^ sw bits).
#pragma unroll
        for (int q = 0; q < 4; q++) {
            int fidx = q * 256 + tid;        // 0..1023
            int r  = fidx >> 3;              // 0..127
            int kq = (fidx & 7) * 4;         // 0,4,...,28
            int gr = rowBase + r;
            float4 v = (gr < NN) ? *(const float4*)(X + (size_t)gr * 128 + kb + kq)
                                 : make_float4(0.f, 0.f, 0.f, 0.f);
            int rs = r ^ ((kq >> 2) & 7) * 4;
            xs[kq + 0][rs] = v.x;
            xs[kq + 1][rs] = v.y;
            xs[kq + 2][rs] = v.z;
            xs[kq + 3][rs] = v.w;
        }
        // fill ws: W rows kb..kb+32 are 4096 contiguous floats
        {
            const float4* wsrc = (const float4*)(W + kb * 128);
            float4* wdst = (float4*)ws;
#pragma unroll
            for (int j = 0; j < 4; j++) wdst[j * 256 + tid] = wsrc[j * 256 + tid];
        }
        __syncthreads();

#pragma unroll
        for (int k = 0; k < 32; k++) {
            int sw = ((k >> 2) & 7) * 4;
            float4 xv = *(const float4*)&xs[k][(lane * 4) ^ sw];
            unsigned long long d0 = pack2(xv.x, xv.x);
            unsigned long long d1 = pack2(xv.y, xv.y);
            unsigned long long d2 = pack2(xv.z, xv.z);
            unsigned long long d3 = pack2(xv.w, xv.w);
            ulonglong2 wa = *(const ulonglong2*)&ws[k][wrp * 16];
            ulonglong2 wb = *(const ulonglong2*)&ws[k][wrp * 16 + 4];
            ulonglong2 wc = *(const ulonglong2*)&ws[k][wrp * 16 + 8];
            ulonglong2 wd = *(const ulonglong2*)&ws[k][wrp * 16 + 12];
            ffma2(acc[0][0], d0, wa.x); ffma2(acc[0][1], d0, wa.y);
            ffma2(acc[0][2], d0, wb.x); ffma2(acc[0][3], d0, wb.y);
            ffma2(acc[0][4], d0, wc.x); ffma2(acc[0][5], d0, wc.y);
            ffma2(acc[0][6], d0, wd.x); ffma2(acc[0][7], d0, wd.y);
            ffma2(acc[1][0], d1, wa.x); ffma2(acc[1][1], d1, wa.y);
            ffma2(acc[1][2], d1, wb.x); ffma2(acc[1][3], d1, wb.y);
            ffma2(acc[1][4], d1, wc.x); ffma2(acc[1][5], d1, wc.y);
            ffma2(acc[1][6], d1, wd.x); ffma2(acc[1][7], d1, wd.y);
            ffma2(acc[2][0], d2, wa.x); ffma2(acc[2][1], d2, wa.y);
            ffma2(acc[2][2], d2, wb.x); ffma2(acc[2][3], d2, wb.y);
            ffma2(acc[2][4], d2, wc.x); ffma2(acc[2][5], d2, wc.y);
            ffma2(acc[2][6], d2, wd.x); ffma2(acc[2][7], d2, wd.y);
            ffma2(acc[3][0], d3, wa.x); ffma2(acc[3][1], d3, wa.y);
            ffma2(acc[3][2], d3, wb.x); ffma2(acc[3][3], d3, wb.y);
            ffma2(acc[3][4], d3, wc.x); ffma2(acc[3][5], d3, wc.y);
            ffma2(acc[3][6], d3, wd.x); ffma2(acc[3][7], d3, wd.y);
        }
        __syncthreads();
    }

    // epilogue: warp owns full head 'wrp' -> attention dots are thread-local
    float av[16], dv[16];
#pragma unroll
    for (int j = 0; j < 16; j++) { av[j] = Asrc[wrp * 16 + j]; dv[j] = Adst[wrp * 16 + j]; }

#pragma unroll
    for (int ri = 0; ri < 4; ri++) {
        int gr = rowBase + lane * 4 + ri;
        if (gr >= NN) continue;
        float c[16];
#pragma unroll
        for (int cp = 0; cp < 8; cp++) unpack2(acc[ri][cp], c[cp * 2], c[cp * 2 + 1]);
        float ps = 0.f, pd = 0.f;
#pragma unroll
        for (int j = 0; j < 16; j++) { ps += c[j] * av[j]; pd += c[j] * dv[j]; }
        float* hrow = &g_h1[(size_t)gr * 128 + wrp * 16];
        *(float4*)(hrow + 0)  = make_float4(c[0],  c[1],  c[2],  c[3]);
        *(float4*)(hrow + 4)  = make_float4(c[4],  c[5],  c[6],  c[7]);
        *(float4*)(hrow + 8)  = make_float4(c[8],  c[9],  c[10], c[11]);
        *(float4*)(hrow + 12) = make_float4(c[12], c[13], c[14], c[15]);
        g_as1[gr * 8 + wrp] = ps;
        g_ad1[gr * 8 + wrp] = pd;
    }
}

// ---------------- layer 1 aggregation: warp per target node, single pass ----------------
__global__ void agg1_k(const float* __restrict__ b1) {
    int warp = (blockIdx.x * blockDim.x + threadIdx.x) >> 5;
    int lane = threadIdx.x & 31;
    if (warp >= NN) return;
    int t = warp;
    int beg = g_rowptr[t], end = g_rowptr[t + 1];

    int hd = lane >> 2;                       // head for this lane's channels
    float adh = g_ad1[t * 8 + hd];
    float4 acc = make_float4(0.f, 0.f, 0.f, 0.f);
    float sumw = 0.f;
    int sN = g_csrsrc[beg];
    for (int idx = beg; idx < end; idx++) {
        int s = sN;
        if (idx + 1 < end) sN = g_csrsrc[idx + 1];
        float v = g_as1[s * 8 + hd] + adh;
        v = v > 0.f ? v : 0.2f * v;
        float w = __expf(v);
        sumw += w;
        float4 hv = *(const float4*)&g_h1[(size_t)s * 128 + lane * 4];
        acc.x += w * hv.x;
        acc.y += w * hv.y;
        acc.z += w * hv.z;
        acc.w += w * hv.w;
    }
    float inv = 1.f / (sumw + 1e-16f);
    int c0 = lane * 4;
    float o0 = acc.x * inv + b1[c0 + 0];
    float o1 = acc.y * inv + b1[c0 + 1];
    float o2 = acc.z * inv + b1[c0 + 2];
    float o3 = acc.w * inv + b1[c0 + 3];
    // ELU
    o0 = o0 > 0.f ? o0 : __expf(o0) - 1.f;
    o1 = o1 > 0.f ? o1 : __expf(o1) - 1.f;
    o2 = o2 > 0.f ? o2 : __expf(o2) - 1.f;
    o3 = o3 > 0.f ? o3 : __expf(o3) - 1.f;
    *(float4*)&g_act1[(size_t)t * 128 + c0] = make_float4(o0, o1, o2, o3);
}

// ---------------- layer 2 GEMM (128 -> 16) + attention coefficients, fused ----------------
__global__ void gemm2_k(const float* __restrict__ W2,
                        const float* __restrict__ Asrc, const float* __restrict__ Adst) {
    __shared__ float w2s[128 * 16];
    int t = threadIdx.x;   // 128
#pragma unroll
    for (int j = 0; j < 16; j++) w2s[j * 128 + t] = W2[j * 128 + t];
    __syncthreads();
    int n = blockIdx.x * 128 + t;
    if (n >= NN) return;

    float acc[16];
#pragma unroll
    for (int c = 0; c < 16; c++) acc[c] = 0.f;

    const float4* xp = (const float4*)&g_act1[(size_t)n * 128];
#pragma unroll 4
    for (int k4 = 0; k4 < 32; k4++) {
        float4 xv = xp[k4];
#pragma unroll
        for (int j = 0; j < 4; j++) {
            int k = k4 * 4 + j;
            float xk = (j == 0) ? xv.x : (j == 1) ? xv.y : (j == 2) ? xv.z : xv.w;
            const float4* wr = (const float4*)&w2s[k * 16];
            float4 w0 = wr[0], w1 = wr[1], w2v = wr[2], w3 = wr[3];
            acc[0]  += xk * w0.x;  acc[1]  += xk * w0.y;  acc[2]  += xk * w0.z;  acc[3]  += xk * w0.w;
            acc[4]  += xk * w1.x;  acc[5]  += xk * w1.y;  acc[6]  += xk * w1.z;  acc[7]  += xk * w1.w;
            acc[8]  += xk * w2v.x; acc[9]  += xk * w2v.y; acc[10] += xk * w2v.z; acc[11] += xk * w2v.w;
            acc[12] += xk * w3.x;  acc[13] += xk * w3.y;  acc[14] += xk * w3.z;  acc[15] += xk * w3.w;
        }
    }
    float s = 0.f, d = 0.f;
#pragma unroll
    for (int c = 0; c < 16; c++) { s += acc[c] * Asrc[c]; d += acc[c] * Adst[c]; }
    float4* hp = (float4*)&g_h2[n * 16];
    hp[0] = make_float4(acc[0],  acc[1],  acc[2],  acc[3]);
    hp[1] = make_float4(acc[4],  acc[5],  acc[6],  acc[7]);
    hp[2] = make_float4(acc[8],  acc[9],  acc[10], acc[11]);
    hp[3] = make_float4(acc[12], acc[13], acc[14], acc[15]);
    g_as2[n] = s;
    g_ad2[n] = d;
}

// ---------------- layer 2 aggregation: warp per target node, single pass ----------------
__global__ void agg2_k(const float* __restrict__ b2, float* __restrict__ out) {
    int warp = (blockIdx.x * blockDim.x + threadIdx.x) >> 5;
    int lane = threadIdx.x & 31;
    if (warp >= NN) return;
    int t = warp;
    int beg = g_rowptr[t], end = g_rowptr[t + 1];
    float adv = g_ad2[t];

    int c = lane & 15;
    float acc = 0.f, sumw = 0.f;
    for (int base = beg; base < end; base += 2) {
        int idx = base + (lane >> 4);
        if (idx < end) {
            int s = g_csrsrc[idx];
            float v = g_as2[s] + adv;
            v = v > 0.f ? v : 0.2f * v;
            float w = __expf(v);
            sumw += w;
            acc += w * g_h2[s * 16 + c];
        }
    }
    sumw += __shfl_xor_sync(0xffffffffu, sumw, 16);
    acc  += __shfl_xor_sync(0xffffffffu, acc, 16);
    if (lane < 16) out[t * 16 + c] = acc / (sumw + 1e-16f) + b2[c];
}

// ---------------- launch ----------------
// CSR build (default stream) runs concurrently with gemm1 (side stream):
// they touch disjoint data. Fork/join via events (graph-capture-legal pattern).
extern "C" void kernel_launch(void* const* d_in, const int* in_sizes, int n_in,
                              void* d_out, int out_size) {
    const float* x    = (const float*)d_in[0];
    const int*   ei   = (const int*)  d_in[1];
    const float* W1   = (const float*)d_in[2];
    const float* as1  = (const float*)d_in[3];
    const float* ad1  = (const float*)d_in[4];
    const float* b1   = (const float*)d_in[5];
    const float* W2   = (const float*)d_in[6];
    const float* as2  = (const float*)d_in[7];
    const float* ad2  = (const float*)d_in[8];
    const float* b2   = (const float*)d_in[9];
    float* out = (float*)d_out;

    static cudaStream_t s1 = nullptr;
    static cudaEvent_t evFork = nullptr, evJoin = nullptr;
    if (s1 == nullptr) {
        cudaStreamCreateWithFlags(&s1, cudaStreamNonBlocking);
        cudaEventCreateWithFlags(&evFork, cudaEventDisableTiming);
        cudaEventCreateWithFlags(&evJoin, cudaEventDisableTiming);
    }

    // fork point: side stream may start gemm1 immediately
    cudaEventRecord(evFork, 0);
    cudaStreamWaitEvent(s1, evFork, 0);

    // CSR build on default stream (launches 1-3)
    zero_k   <<<(NN + 255) / 256, 256>>>();
    hist_k   <<<(ET + 255) / 256, 256>>>(ei);
    scan1_k  <<<NB_SCAN, 1024>>>();

    // gemm1 on side stream
    gemm1_k  <<<(NN + 127) / 128, 256, 0, s1>>>(x, W1, as1, ad1);

    // rest of CSR build on default stream
    scan2_k  <<<1, 128>>>();
    scan3_k  <<<NB_SCAN, 1024>>>();
    scatter_k<<<(ET + 255) / 256, 256>>>(ei);

    // join: aggregation needs both CSR and gemm1
    cudaEventRecord(evJoin, s1);
    cudaStreamWaitEvent(0, evJoin, 0);

    agg1_k   <<<(NN + 7) / 8, 256>>>(b1);
    gemm2_k  <<<(NN + 127) / 128, 128>>>(W2, as2, ad2);
    agg2_k   <<<(NN + 7) / 8, 256>>>(b2, out);
}

// round 14
// speedup vs baseline: 1.0895x; 1.0895x over previous
#include <cuda_runtime.h>
#include <math.h>

#define NN 100000
#define EE 1600000
#define ET (EE + NN)
#define NB_SCAN ((NN + 1023) / 1024)   // 98

// ---------------- scratch (static device globals; no allocation) ----------------
__device__ int   g_deg[NN];
__device__ int   g_fill[NN];
__device__ int   g_rowptr[NN + 1];
__device__ int   g_csrsrc[ET];
__device__ int   g_bsum[128];
__device__ int   g_total;
__device__ float g_h1[NN * 128];
__device__ float g_as1[NN * 8];
__device__ float g_ad1[NN * 8];
__device__ float g_act1[NN * 128];
__device__ float g_h2[NN * 16];
__device__ float g_as2[NN];
__device__ float g_ad2[NN];

// ---------------- f32x2 helpers ----------------
__device__ __forceinline__ void ffma2(unsigned long long& d, unsigned long long a,
                                      unsigned long long b) {
    asm("fma.rn.f32x2 %0, %1, %2, %0;" : "+l"(d) : "l"(a), "l"(b));
}
__device__ __forceinline__ unsigned long long pack2(float lo, float hi) {
    unsigned long long r;
    asm("mov.b64 %0, {%1, %2};" : "=l"(r) : "f"(lo), "f"(hi));
    return r;
}
__device__ __forceinline__ void unpack2(unsigned long long v, float& lo, float& hi) {
    asm("mov.b64 {%0, %1}, %2;" : "=f"(lo), "=f"(hi) : "l"(v));
}

// ---------------- CSR build ----------------
__global__ void zero_k() {
    int i = blockIdx.x * blockDim.x + threadIdx.x;
    if (i < NN) { g_deg[i] = 0; g_fill[i] = 0; }
}

__global__ void hist_k(const int* __restrict__ ei) {
    int i = blockIdx.x * blockDim.x + threadIdx.x;
    if (i >= ET) return;
    int t = (i < EE) ? ei[EE + i] : (i - EE);   // self-loop tail
    atomicAdd(&g_deg[t], 1);
}

__global__ void scan1_k() {
    __shared__ int sh[1024];
    int t = threadIdx.x;
    int i = blockIdx.x * 1024 + t;
    int v = (i < NN) ? g_deg[i] : 0;
    sh[t] = v;
    __syncthreads();
    for (int off = 1; off < 1024; off <<= 1) {
        int add = (t >= off) ? sh[t - off] : 0;
        __syncthreads();
        sh[t] += add;
        __syncthreads();
    }
    if (i < NN) g_rowptr[i] = sh[t] - v;        // exclusive within block
    if (t == 1023) g_bsum[blockIdx.x] = sh[1023];
}

__global__ void scan2_k() {
    __shared__ int sh[128];
    int t = threadIdx.x;
    int v = (t < NB_SCAN) ? g_bsum[t] : 0;
    sh[t] = v;
    __syncthreads();
    for (int off = 1; off < 128; off <<= 1) {
        int add = (t >= off) ? sh[t - off] : 0;
        __syncthreads();
        sh[t] += add;
        __syncthreads();
    }
    if (t < NB_SCAN) g_bsum[t] = sh[t] - v;     // exclusive block offsets
    if (t == 127) g_total = sh[127];
}

__global__ void scan3_k() {
    int i = blockIdx.x * 1024 + threadIdx.x;
    if (i < NN) g_rowptr[i] += g_bsum[blockIdx.x];
    if (i == 0) g_rowptr[NN] = g_total;
}

__global__ void scatter_k(const int* __restrict__ ei) {
    int i = blockIdx.x * blockDim.x + threadIdx.x;
    if (i >= ET) return;
    int s, t;
    if (i < EE) { s = ei[i]; t = ei[EE + i]; }
    else        { s = i - EE; t = i - EE; }
    int pos = atomicAdd(&g_fill[t], 1);
    g_csrsrc[g_rowptr[t] + pos] = s;
}

// ---------------- layer 1 GEMM via FFMA2: h1 = x @ W1 (128x128) + fused attn coeffs
// Block tile 128 rows x 64 cols, grid (rowblocks, 2), 256 threads (8 warps).
// Warp w owns cols w*8..w*8+8 (= half of head w>>1); lane owns rows lane*4..+3.
// Thread tile 4x8 = 16 f32x2 accumulators (32 regs). Per k-step: 1 LDS.128 (x)
// + 2 LDS.128 (w, broadcast) feed 64 FMAs -> low L1 pressure AND low reg count
// (R11 was L1-bound at 80%; R12's 4x16 tile fixed L1 but hit 130 regs / 12% occ).
// Attention partials (half-head) are combined via an smem scratch reduction.
__global__ __launch_bounds__(256, 3) void gemm1_k(const float* __restrict__ X,
                                                  const float* __restrict__ W,
                                                  const float* __restrict__ Asrc,
                                                  const float* __restrict__ Adst) {
    __shared__ float xs[32][128];   // [k][row^swizzle] 16KB (reused as scratch)
    __shared__ float ws[32][64];    // [k][col]          8KB
    int tid  = threadIdx.x;         // 256
    int wrp  = tid >> 5;            // 0..7 = 8-col group
    int lane = tid & 31;            // rows lane*4 .. lane*4+3
    int rowBase = blockIdx.x * 128;
    int colBase = blockIdx.y * 64;  // 0 or 64

    unsigned long long acc[4][4];
#pragma unroll
    for (int i = 0; i < 4; i++)
#pragma unroll
        for (int j = 0; j < 4; j++) acc[i][j] = 0ull;

    for (int kb = 0; kb < 128; kb += 32) {
        // fill xs: 128 rows x 32 k; 4 coalesced float4 loads per thread,
        // scattered as swizzled STS.32 (conflict-free: r low bits ^ sw bits).
#pragma unroll
        for (int q = 0; q < 4; q++) {
            int fidx = q * 256 + tid;        // 0..1023
            int r  = fidx >> 3;              // 0..127
            int kq = (fidx & 7) * 4;         // 0,4,...,28
            int gr = rowBase + r;
            float4 v = (gr < NN) ? *(const float4*)(X + (size_t)gr * 128 + kb + kq)
                                 : make_float4(0.f, 0.f, 0.f, 0.f);
            int rs = r ^ ((kq >> 2) & 7) * 4;
            xs[kq + 0][rs] = v.x;
            xs[kq + 1][rs] = v.y;
            xs[kq + 2][rs] = v.z;
            xs[kq + 3][rs] = v.w;
        }
        // fill ws: 32 k x 64 cols = 2048 floats; 2 float4s per thread
#pragma unroll
        for (int q = 0; q < 2; q++) {
            int fidx = q * 256 + tid;        // 0..511
            int k  = fidx >> 4;              // 0..31
            int c4 = (fidx & 15) * 4;        // 0..60
            *(float4*)&ws[k][c4] = *(const float4*)(W + (kb + k) * 128 + colBase + c4);
        }
        __syncthreads();

#pragma unroll
        for (int k = 0; k < 32; k++) {
            int sw = ((k >> 2) & 7) * 4;
            float4 xv = *(const float4*)&xs[k][(lane * 4) ^ sw];
            unsigned long long d0 = pack2(xv.x, xv.x);
            unsigned long long d1 = pack2(xv.y, xv.y);
            unsigned long long d2 = pack2(xv.z, xv.z);
            unsigned long long d3 = pack2(xv.w, xv.w);
            ulonglong2 wa = *(const ulonglong2*)&ws[k][wrp * 8];
            ulonglong2 wb = *(const ulonglong2*)&ws[k][wrp * 8 + 4];
            ffma2(acc[0][0], d0, wa.x); ffma2(acc[0][1], d0, wa.y);
            ffma2(acc[0][2], d0, wb.x); ffma2(acc[0][3], d0, wb.y);
            ffma2(acc[1][0], d1, wa.x); ffma2(acc[1][1], d1, wa.y);
            ffma2(acc[1][2], d1, wb.x); ffma2(acc[1][3], d1, wb.y);
            ffma2(acc[2][0], d2, wa.x); ffma2(acc[2][1], d2, wa.y);
            ffma2(acc[2][2], d2, wb.x); ffma2(acc[2][3], d2, wb.y);
            ffma2(acc[3][0], d3, wa.x); ffma2(acc[3][1], d3, wa.y);
            ffma2(acc[3][2], d3, wb.x); ffma2(acc[3][3], d3, wb.y);
        }
        __syncthreads();
    }

    // epilogue: h1 store + half-head attention partials into smem scratch
    float av[8], dv[8];
#pragma unroll
    for (int j = 0; j < 8; j++) {
        av[j] = Asrc[colBase + wrp * 8 + j];
        dv[j] = Adst[colBase + wrp * 8 + j];
    }

    float2* sh = (float2*)xs;       // scratch [8 warps][128 rows] of (ps,pd)
#pragma unroll
    for (int ri = 0; ri < 4; ri++) {
        int r  = lane * 4 + ri;
        int gr = rowBase + r;
        float c[8];
#pragma unroll
        for (int cp = 0; cp < 4; cp++) unpack2(acc[ri][cp], c[cp * 2], c[cp * 2 + 1]);
        float ps = 0.f, pd = 0.f;
#pragma unroll
        for (int j = 0; j < 8; j++) { ps += c[j] * av[j]; pd += c[j] * dv[j]; }
        if (gr < NN) {
            float* hrow = &g_h1[(size_t)gr * 128 + colBase + wrp * 8];
            *(float4*)(hrow + 0) = make_float4(c[0], c[1], c[2], c[3]);
            *(float4*)(hrow + 4) = make_float4(c[4], c[5], c[6], c[7]);
        }
        sh[wrp * 128 + r] = make_float2(ps, pd);
    }
    __syncthreads();

    // combine warp pairs (2h, 2h+1) -> head h; 4 heads x 128 rows = 512 entries
#pragma unroll
    for (int e = tid; e < 512; e += 256) {
        int h = e >> 7, r = e & 127;
        int gr = rowBase + r;
        if (gr < NN) {
            float2 a = sh[(2 * h) * 128 + r];
            float2 b = sh[(2 * h + 1) * 128 + r];
            int hg = (colBase >> 4) + h;     // global head index
            g_as1[gr * 8 + hg] = a.x + b.x;
            g_ad1[gr * 8 + hg] = a.y + b.y;
        }
    }
}

// ---------------- layer 1 aggregation: warp per target node, single pass ----------------
__global__ void agg1_k(const float* __restrict__ b1) {
    int warp = (blockIdx.x * blockDim.x + threadIdx.x) >> 5;
    int lane = threadIdx.x & 31;
    if (warp >= NN) return;
    int t = warp;
    int beg = g_rowptr[t], end = g_rowptr[t + 1];

    int hd = lane >> 2;                       // head for this lane's channels
    float adh = g_ad1[t * 8 + hd];
    float4 acc = make_float4(0.f, 0.f, 0.f, 0.f);
    float sumw = 0.f;
    int sN = g_csrsrc[beg];
    for (int idx = beg; idx < end; idx++) {
        int s = sN;
        if (idx + 1 < end) sN = g_csrsrc[idx + 1];
        float v = g_as1[s * 8 + hd] + adh;
        v = v > 0.f ? v : 0.2f * v;
        float w = __expf(v);
        sumw += w;
        float4 hv = *(const float4*)&g_h1[(size_t)s * 128 + lane * 4];
        acc.x += w * hv.x;
        acc.y += w * hv.y;
        acc.z += w * hv.z;
        acc.w += w * hv.w;
    }
    float inv = 1.f / (sumw + 1e-16f);
    int c0 = lane * 4;
    float o0 = acc.x * inv + b1[c0 + 0];
    float o1 = acc.y * inv + b1[c0 + 1];
    float o2 = acc.z * inv + b1[c0 + 2];
    float o3 = acc.w * inv + b1[c0 + 3];
    // ELU
    o0 = o0 > 0.f ? o0 : __expf(o0) - 1.f;
    o1 = o1 > 0.f ? o1 : __expf(o1) - 1.f;
    o2 = o2 > 0.f ? o2 : __expf(o2) - 1.f;
    o3 = o3 > 0.f ? o3 : __expf(o3) - 1.f;
    *(float4*)&g_act1[(size_t)t * 128 + c0] = make_float4(o0, o1, o2, o3);
}

// ---------------- layer 2 GEMM (128 -> 16) + attention coefficients, fused ----------------
__global__ void gemm2_k(const float* __restrict__ W2,
                        const float* __restrict__ Asrc, const float* __restrict__ Adst) {
    __shared__ float w2s[128 * 16];
    int t = threadIdx.x;   // 128
#pragma unroll
    for (int j = 0; j < 16; j++) w2s[j * 128 + t] = W2[j * 128 + t];
    __syncthreads();
    int n = blockIdx.x * 128 + t;
    if (n >= NN) return;

    float acc[16];
#pragma unroll
    for (int c = 0; c < 16; c++) acc[c] = 0.f;

    const float4* xp = (const float4*)&g_act1[(size_t)n * 128];
#pragma unroll 4
    for (int k4 = 0; k4 < 32; k4++) {
        float4 xv = xp[k4];
#pragma unroll
        for (int j = 0; j < 4; j++) {
            int k = k4 * 4 + j;
            float xk = (j == 0) ? xv.x : (j == 1) ? xv.y : (j == 2) ? xv.z : xv.w;
            const float4* wr = (const float4*)&w2s[k * 16];
            float4 w0 = wr[0], w1 = wr[1], w2v = wr[2], w3 = wr[3];
            acc[0]  += xk * w0.x;  acc[1]  += xk * w0.y;  acc[2]  += xk * w0.z;  acc[3]  += xk * w0.w;
            acc[4]  += xk * w1.x;  acc[5]  += xk * w1.y;  acc[6]  += xk * w1.z;  acc[7]  += xk * w1.w;
            acc[8]  += xk * w2v.x; acc[9]  += xk * w2v.y; acc[10] += xk * w2v.z; acc[11] += xk * w2v.w;
            acc[12] += xk * w3.x;  acc[13] += xk * w3.y;  acc[14] += xk * w3.z;  acc[15] += xk * w3.w;
        }
    }
    float s = 0.f, d = 0.f;
#pragma unroll
    for (int c = 0; c < 16; c++) { s += acc[c] * Asrc[c]; d += acc[c] * Adst[c]; }
    float4* hp = (float4*)&g_h2[n * 16];
    hp[0] = make_float4(acc[0],  acc[1],  acc[2],  acc[3]);
    hp[1] = make_float4(acc[4],  acc[5],  acc[6],  acc[7]);
    hp[2] = make_float4(acc[8],  acc[9],  acc[10], acc[11]);
    hp[3] = make_float4(acc[12], acc[13], acc[14], acc[15]);
    g_as2[n] = s;
    g_ad2[n] = d;
}

// ---------------- layer 2 aggregation: warp per target node, single pass ----------------
__global__ void agg2_k(const float* __restrict__ b2, float* __restrict__ out) {
    int warp = (blockIdx.x * blockDim.x + threadIdx.x) >> 5;
    int lane = threadIdx.x & 31;
    if (warp >= NN) return;
    int t = warp;
    int beg = g_rowptr[t], end = g_rowptr[t + 1];
    float adv = g_ad2[t];

    int c = lane & 15;
    float acc = 0.f, sumw = 0.f;
    for (int base = beg; base < end; base += 2) {
        int idx = base + (lane >> 4);
        if (idx < end) {
            int s = g_csrsrc[idx];
            float v = g_as2[s] + adv;
            v = v > 0.f ? v : 0.2f * v;
            float w = __expf(v);
            sumw += w;
            acc += w * g_h2[s * 16 + c];
        }
    }
    sumw += __shfl_xor_sync(0xffffffffu, sumw, 16);
    acc  += __shfl_xor_sync(0xffffffffu, acc, 16);
    if (lane < 16) out[t * 16 + c] = acc / (sumw + 1e-16f) + b2[c];
}

// ---------------- launch ----------------
// CSR build (default stream) runs concurrently with gemm1 (side stream):
// they touch disjoint data. Fork/join via events (graph-capture-legal pattern).
extern "C" void kernel_launch(void* const* d_in, const int* in_sizes, int n_in,
                              void* d_out, int out_size) {
    const float* x    = (const float*)d_in[0];
    const int*   ei   = (const int*)  d_in[1];
    const float* W1   = (const float*)d_in[2];
    const float* as1  = (const float*)d_in[3];
    const float* ad1  = (const float*)d_in[4];
    const float* b1   = (const float*)d_in[5];
    const float* W2   = (const float*)d_in[6];
    const float* as2  = (const float*)d_in[7];
    const float* ad2  = (const float*)d_in[8];
    const float* b2   = (const float*)d_in[9];
    float* out = (float*)d_out;

    static cudaStream_t s1 = nullptr;
    static cudaEvent_t evFork = nullptr, evJoin = nullptr;
    if (s1 == nullptr) {
        cudaStreamCreateWithFlags(&s1, cudaStreamNonBlocking);
        cudaEventCreateWithFlags(&evFork, cudaEventDisableTiming);
        cudaEventCreateWithFlags(&evJoin, cudaEventDisableTiming);
    }

    // fork point: side stream may start gemm1 immediately
    cudaEventRecord(evFork, 0);
    cudaStreamWaitEvent(s1, evFork, 0);

    // CSR build on default stream (launches 1-3)
    zero_k   <<<(NN + 255) / 256, 256>>>();
    hist_k   <<<(ET + 255) / 256, 256>>>(ei);
    scan1_k  <<<NB_SCAN, 1024>>>();

    // gemm1 on side stream
    {
        dim3 grid((NN + 127) / 128, 2);
        gemm1_k<<<grid, 256, 0, s1>>>(x, W1, as1, ad1);
    }

    // rest of CSR build on default stream
    scan2_k  <<<1, 128>>>();
    scan3_k  <<<NB_SCAN, 1024>>>();
    scatter_k<<<(ET + 255) / 256, 256>>>(ei);

    // join: aggregation needs both CSR and gemm1
    cudaEventRecord(evJoin, s1);
    cudaStreamWaitEvent(0, evJoin, 0);

    agg1_k   <<<(NN + 7) / 8, 256>>>(b1);
    gemm2_k  <<<(NN + 127) / 128, 128>>>(W2, as2, ad2);
    agg2_k   <<<(NN + 7) / 8, 256>>>(b2, out);
}

// round 17
// speedup vs baseline: 1.1337x; 1.0405x over previous
#include <cuda_runtime.h>
#include <cuda_fp16.h>
#include <math.h>

#define NN 100000
#define EE 1600000
#define ET (EE + NN)
#define NB_SCAN ((NN + 1023) / 1024)   // 98

// ---------------- scratch (static device globals; no allocation) ----------------
__device__ int    g_deg[NN];
__device__ int    g_fill[NN];
__device__ int    g_rowptr[NN + 1];
__device__ int    g_csrsrc[ET];
__device__ int    g_bsum[128];
__device__ int    g_total;
__device__ __half g_h1[NN * 128];    // fp16: gathered 17x per node by agg1
__device__ float  g_as1[NN * 8];
__device__ float  g_ad1[NN * 8];
__device__ float  g_act1[NN * 128];
__device__ __half g_h2[NN * 16];     // fp16: gathered by agg2
__device__ float  g_as2[NN];
__device__ float  g_ad2[NN];

// ---------------- f32x2 / half2 helpers ----------------
__device__ __forceinline__ void ffma2(unsigned long long& d, unsigned long long a,
                                      unsigned long long b) {
    asm("fma.rn.f32x2 %0, %1, %2, %0;" : "+l"(d) : "l"(a), "l"(b));
}
__device__ __forceinline__ unsigned long long pack2(float lo, float hi) {
    unsigned long long r;
    asm("mov.b64 %0, {%1, %2};" : "=l"(r) : "f"(lo), "f"(hi));
    return r;
}
__device__ __forceinline__ void unpack2(unsigned long long v, float& lo, float& hi) {
    asm("mov.b64 {%0, %1}, %2;" : "=f"(lo), "=f"(hi) : "l"(v));
}
union H2U4 { uint4 u; __half2 h[4]; };
union H2U2 { uint2 u; __half2 h[2]; };

// ---------------- CSR build ----------------
__global__ void zero_k() {
    int i = blockIdx.x * blockDim.x + threadIdx.x;
    if (i < NN) { g_deg[i] = 0; g_fill[i] = 0; }
}

__global__ void hist_k(const int* __restrict__ ei) {
    int i = blockIdx.x * blockDim.x + threadIdx.x;
    if (i >= ET) return;
    int t = (i < EE) ? ei[EE + i] : (i - EE);   // self-loop tail
    atomicAdd(&g_deg[t], 1);
}

__global__ void scan1_k() {
    __shared__ int sh[1024];
    int t = threadIdx.x;
    int i = blockIdx.x * 1024 + t;
    int v = (i < NN) ? g_deg[i] : 0;
    sh[t] = v;
    __syncthreads();
    for (int off = 1; off < 1024; off <<= 1) {
        int add = (t >= off) ? sh[t - off] : 0;
        __syncthreads();
        sh[t] += add;
        __syncthreads();
    }
    if (i < NN) g_rowptr[i] = sh[t] - v;        // exclusive within block
    if (t == 1023) g_bsum[blockIdx.x] = sh[1023];
}

__global__ void scan2_k() {
    __shared__ int sh[128];
    int t = threadIdx.x;
    int v = (t < NB_SCAN) ? g_bsum[t] : 0;
    sh[t] = v;
    __syncthreads();
    for (int off = 1; off < 128; off <<= 1) {
        int add = (t >= off) ? sh[t - off] : 0;
        __syncthreads();
        sh[t] += add;
        __syncthreads();
    }
    if (t < NB_SCAN) g_bsum[t] = sh[t] - v;     // exclusive block offsets
    if (t == 127) g_total = sh[127];
}

__global__ void scan3_k() {
    int i = blockIdx.x * 1024 + threadIdx.x;
    if (i < NN) g_rowptr[i] += g_bsum[blockIdx.x];
    if (i == 0) g_rowptr[NN] = g_total;
}

__global__ void scatter_k(const int* __restrict__ ei) {
    int i = blockIdx.x * blockDim.x + threadIdx.x;
    if (i >= ET) return;
    int s, t;
    if (i < EE) { s = ei[i]; t = ei[EE + i]; }
    else        { s = i - EE; t = i - EE; }
    int pos = atomicAdd(&g_fill[t], 1);
    g_csrsrc[g_rowptr[t] + pos] = s;
}

// ---------------- layer 1 GEMM via FFMA2: h1 = x @ W1 (128x128) + fused attn coeffs
// Block tile 128 rows x 64 cols, grid (rowblocks, 2), 256 threads (8 warps).
// Warp w owns cols w*8..w*8+8; lane owns rows lane*4..+3 (4x8 thread tile).
// Attention partials (fp32) combined via smem scratch; h1 stored as fp16.
__global__ __launch_bounds__(256, 3) void gemm1_k(const float* __restrict__ X,
                                                  const float* __restrict__ W,
                                                  const float* __restrict__ Asrc,
                                                  const float* __restrict__ Adst) {
    __shared__ float xs[32][128];   // [k][row^swizzle] 16KB (reused as scratch)
    __shared__ float ws[32][64];    // [k][col]          8KB
    int tid  = threadIdx.x;         // 256
    int wrp  = tid >> 5;            // 0..7 = 8-col group
    int lane = tid & 31;            // rows lane*4 .. lane*4+3
    int rowBase = blockIdx.x * 128;
    int colBase = blockIdx.y * 64;  // 0 or 64

    unsigned long long acc[4][4];
#pragma unroll
    for (int i = 0; i < 4; i++)
#pragma unroll
        for (int j = 0; j < 4; j++) acc[i][j] = 0ull;

    for (int kb = 0; kb < 128; kb += 32) {
#pragma unroll
        for (int q = 0; q < 4; q++) {
            int fidx = q * 256 + tid;        // 0..1023
            int r  = fidx >> 3;              // 0..127
            int kq = (fidx & 7) * 4;         // 0,4,...,28
            int gr = rowBase + r;
            float4 v = (gr < NN) ? *(const float4*)(X + (size_t)gr * 128 + kb + kq)
                                 : make_float4(0.f, 0.f, 0.f, 0.f);
            int rs = r ^ ((kq >> 2) & 7) * 4;
            xs[kq + 0][rs] = v.x;
            xs[kq + 1][rs] = v.y;
            xs[kq + 2][rs] = v.z;
            xs[kq + 3][rs] = v.w;
        }
#pragma unroll
        for (int q = 0; q < 2; q++) {
            int fidx = q * 256 + tid;        // 0..511
            int k  = fidx >> 4;              // 0..31
            int c4 = (fidx & 15) * 4;        // 0..60
            *(float4*)&ws[k][c4] = *(const float4*)(W + (kb + k) * 128 + colBase + c4);
        }
        __syncthreads();

#pragma unroll
        for (int k = 0; k < 32; k++) {
            int sw = ((k >> 2) & 7) * 4;
            float4 xv = *(const float4*)&xs[k][(lane * 4) ^ sw];
            unsigned long long d0 = pack2(xv.x, xv.x);
            unsigned long long d1 = pack2(xv.y, xv.y);
            unsigned long long d2 = pack2(xv.z, xv.z);
            unsigned long long d3 = pack2(xv.w, xv.w);
            ulonglong2 wa = *(const ulonglong2*)&ws[k][wrp * 8];
            ulonglong2 wb = *(const ulonglong2*)&ws[k][wrp * 8 + 4];
            ffma2(acc[0][0], d0, wa.x); ffma2(acc[0][1], d0, wa.y);
            ffma2(acc[0][2], d0, wb.x); ffma2(acc[0][3], d0, wb.y);
            ffma2(acc[1][0], d1, wa.x); ffma2(acc[1][1], d1, wa.y);
            ffma2(acc[1][2], d1, wb.x); ffma2(acc[1][3], d1, wb.y);
            ffma2(acc[2][0], d2, wa.x); ffma2(acc[2][1], d2, wa.y);
            ffma2(acc[2][2], d2, wb.x); ffma2(acc[2][3], d2, wb.y);
            ffma2(acc[3][0], d3, wa.x); ffma2(acc[3][1], d3, wa.y);
            ffma2(acc[3][2], d3, wb.x); ffma2(acc[3][3], d3, wb.y);
        }
        __syncthreads();
    }

    // epilogue: h1 store (fp16) + half-head attention partials (fp32) into scratch
    float av[8], dv[8];
#pragma unroll
    for (int j = 0; j < 8; j++) {
        av[j] = Asrc[colBase + wrp * 8 + j];
        dv[j] = Adst[colBase + wrp * 8 + j];
    }

    float2* sh = (float2*)xs;       // scratch [8 warps][128 rows] of (ps,pd)
#pragma unroll
    for (int ri = 0; ri < 4; ri++) {
        int r  = lane * 4 + ri;
        int gr = rowBase + r;
        float c[8];
#pragma unroll
        for (int cp = 0; cp < 4; cp++) unpack2(acc[ri][cp], c[cp * 2], c[cp * 2 + 1]);
        float ps = 0.f, pd = 0.f;
#pragma unroll
        for (int j = 0; j < 8; j++) { ps += c[j] * av[j]; pd += c[j] * dv[j]; }
        if (gr < NN) {
            // 8 floats -> 4 half2 = one 16B store
            H2U4 pk;
            pk.h[0] = __floats2half2_rn(c[0], c[1]);
            pk.h[1] = __floats2half2_rn(c[2], c[3]);
            pk.h[2] = __floats2half2_rn(c[4], c[5]);
            pk.h[3] = __floats2half2_rn(c[6], c[7]);
            *(uint4*)&g_h1[(size_t)gr * 128 + colBase + wrp * 8] = pk.u;
        }
        sh[wrp * 128 + r] = make_float2(ps, pd);
    }
    __syncthreads();

    // combine warp pairs (2h, 2h+1) -> head h; 4 heads x 128 rows = 512 entries
#pragma unroll
    for (int e = tid; e < 512; e += 256) {
        int h = e >> 7, r = e & 127;
        int gr = rowBase + r;
        if (gr < NN) {
            float2 a = sh[(2 * h) * 128 + r];
            float2 b = sh[(2 * h + 1) * 128 + r];
            int hg = (colBase >> 4) + h;     // global head index
            g_as1[gr * 8 + hg] = a.x + b.x;
            g_ad1[gr * 8 + hg] = a.y + b.y;
        }
    }
}

// ---------------- layer 1 aggregation: warp per target node, single pass ----------------
// h1 gathered as fp16 (256B/edge instead of 512B): agg1 is L2-bandwidth-bound.
__global__ void agg1_k(const float* __restrict__ b1) {
    int warp = (blockIdx.x * blockDim.x + threadIdx.x) >> 5;
    int lane = threadIdx.x & 31;
    if (warp >= NN) return;
    int t = warp;
    int beg = g_rowptr[t], end = g_rowptr[t + 1];

    int hd = lane >> 2;                       // head for this lane's channels
    float adh = g_ad1[t * 8 + hd];
    float4 acc = make_float4(0.f, 0.f, 0.f, 0.f);
    float sumw = 0.f;
    int sN = g_csrsrc[beg];
    for (int idx = beg; idx < end; idx++) {
        int s = sN;
        if (idx + 1 < end) sN = g_csrsrc[idx + 1];
        float v = g_as1[s * 8 + hd] + adh;
        v = v > 0.f ? v : 0.2f * v;
        float w = __expf(v);
        sumw += w;
        H2U2 hv;
        hv.u = *(const uint2*)&g_h1[(size_t)s * 128 + lane * 4];  // 4 halves
        float2 f01 = __half22float2(hv.h[0]);
        float2 f23 = __half22float2(hv.h[1]);
        acc.x += w * f01.x;
        acc.y += w * f01.y;
        acc.z += w * f23.x;
        acc.w += w * f23.y;
    }
    float inv = 1.f / (sumw + 1e-16f);
    int c0 = lane * 4;
    float o0 = acc.x * inv + b1[c0 + 0];
    float o1 = acc.y * inv + b1[c0 + 1];
    float o2 = acc.z * inv + b1[c0 + 2];
    float o3 = acc.w * inv + b1[c0 + 3];
    // ELU
    o0 = o0 > 0.f ? o0 : __expf(o0) - 1.f;
    o1 = o1 > 0.f ? o1 : __expf(o1) - 1.f;
    o2 = o2 > 0.f ? o2 : __expf(o2) - 1.f;
    o3 = o3 > 0.f ? o3 : __expf(o3) - 1.f;
    *(float4*)&g_act1[(size_t)t * 128 + c0] = make_float4(o0, o1, o2, o3);
}

// ---------------- layer 2 GEMM (128 -> 16) + attention coefficients, fused ----------------
__global__ void gemm2_k(const float* __restrict__ W2,
                        const float* __restrict__ Asrc, const float* __restrict__ Adst) {
    __shared__ float w2s[128 * 16];
    int t = threadIdx.x;   // 128
#pragma unroll
    for (int j = 0; j < 16; j++) w2s[j * 128 + t] = W2[j * 128 + t];
    __syncthreads();
    int n = blockIdx.x * 128 + t;
    if (n >= NN) return;

    float acc[16];
#pragma unroll
    for (int c = 0; c < 16; c++) acc[c] = 0.f;

    const float4* xp = (const float4*)&g_act1[(size_t)n * 128];
#pragma unroll 4
    for (int k4 = 0; k4 < 32; k4++) {
        float4 xv = xp[k4];
#pragma unroll
        for (int j = 0; j < 4; j++) {
            int k = k4 * 4 + j;
            float xk = (j == 0) ? xv.x : (j == 1) ? xv.y : (j == 2) ? xv.z : xv.w;
            const float4* wr = (const float4*)&w2s[k * 16];
            float4 w0 = wr[0], w1 = wr[1], w2v = wr[2], w3 = wr[3];
            acc[0]  += xk * w0.x;  acc[1]  += xk * w0.y;  acc[2]  += xk * w0.z;  acc[3]  += xk * w0.w;
            acc[4]  += xk * w1.x;  acc[5]  += xk * w1.y;  acc[6]  += xk * w1.z;  acc[7]  += xk * w1.w;
            acc[8]  += xk * w2v.x; acc[9]  += xk * w2v.y; acc[10] += xk * w2v.z; acc[11] += xk * w2v.w;
            acc[12] += xk * w3.x;  acc[13] += xk * w3.y;  acc[14] += xk * w3.z;  acc[15] += xk * w3.w;
        }
    }
    float s = 0.f, d = 0.f;
#pragma unroll
    for (int c = 0; c < 16; c++) { s += acc[c] * Asrc[c]; d += acc[c] * Adst[c]; }
    // h2 stored as fp16: 16 floats -> 8 half2 = two 16B stores
    H2U4 pk0, pk1;
    pk0.h[0] = __floats2half2_rn(acc[0],  acc[1]);
    pk0.h[1] = __floats2half2_rn(acc[2],  acc[3]);
    pk0.h[2] = __floats2half2_rn(acc[4],  acc[5]);
    pk0.h[3] = __floats2half2_rn(acc[6],  acc[7]);
    pk1.h[0] = __floats2half2_rn(acc[8],  acc[9]);
    pk1.h[1] = __floats2half2_rn(acc[10], acc[11]);
    pk1.h[2] = __floats2half2_rn(acc[12], acc[13]);
    pk1.h[3] = __floats2half2_rn(acc[14], acc[15]);
    uint4* hp = (uint4*)&g_h2[(size_t)n * 16];
    hp[0] = pk0.u;
    hp[1] = pk1.u;
    g_as2[n] = s;
    g_ad2[n] = d;
}

// ---------------- layer 2 aggregation: warp per target node, single pass ----------------
__global__ void agg2_k(const float* __restrict__ b2, float* __restrict__ out) {
    int warp = (blockIdx.x * blockDim.x + threadIdx.x) >> 5;
    int lane = threadIdx.x & 31;
    if (warp >= NN) return;
    int t = warp;
    int beg = g_rowptr[t], end = g_rowptr[t + 1];
    float adv = g_ad2[t];

    // two edges per iteration; lane covers channel lane&15, half = lane>>4
    int c = lane & 15;
    float acc = 0.f, sumw = 0.f;
    for (int base = beg; base < end; base += 2) {
        int idx = base + (lane >> 4);
        if (idx < end) {
            int s = g_csrsrc[idx];
            float v = g_as2[s] + adv;
            v = v > 0.f ? v : 0.2f * v;
            float w = __expf(v);
            sumw += w;
            acc += w * __half2float(g_h2[s * 16 + c]);
        }
    }
    sumw += __shfl_xor_sync(0xffffffffu, sumw, 16);
    acc  += __shfl_xor_sync(0xffffffffu, acc, 16);
    if (lane < 16) out[t * 16 + c] = acc / (sumw + 1e-16f) + b2[c];
}

// ---------------- launch ----------------
// CSR build (default stream) runs concurrently with gemm1 (side stream):
// they touch disjoint data. Fork/join via events (graph-capture-legal pattern).
extern "C" void kernel_launch(void* const* d_in, const int* in_sizes, int n_in,
                              void* d_out, int out_size) {
    const float* x    = (const float*)d_in[0];
    const int*   ei   = (const int*)  d_in[1];
    const float* W1   = (const float*)d_in[2];
    const float* as1  = (const float*)d_in[3];
    const float* ad1  = (const float*)d_in[4];
    const float* b1   = (const float*)d_in[5];
    const float* W2   = (const float*)d_in[6];
    const float* as2  = (const float*)d_in[7];
    const float* ad2  = (const float*)d_in[8];
    const float* b2   = (const float*)d_in[9];
    float* out = (float*)d_out;

    static cudaStream_t s1 = nullptr;
    static cudaEvent_t evFork = nullptr, evJoin = nullptr;
    if (s1 == nullptr) {
        cudaStreamCreateWithFlags(&s1, cudaStreamNonBlocking);
        cudaEventCreateWithFlags(&evFork, cudaEventDisableTiming);
        cudaEventCreateWithFlags(&evJoin, cudaEventDisableTiming);
    }

    // fork point: side stream may start gemm1 immediately
    cudaEventRecord(evFork, 0);
    cudaStreamWaitEvent(s1, evFork, 0);

    // CSR build on default stream (launches 1-3)
    zero_k   <<<(NN + 255) / 256, 256>>>();
    hist_k   <<<(ET + 255) / 256, 256>>>(ei);
    scan1_k  <<<NB_SCAN, 1024>>>();

    // gemm1 on side stream
    {
        dim3 grid((NN + 127) / 128, 2);
        gemm1_k<<<grid, 256, 0, s1>>>(x, W1, as1, ad1);
    }

    // rest of CSR build on default stream
    scan2_k  <<<1, 128>>>();
    scan3_k  <<<NB_SCAN, 1024>>>();
    scatter_k<<<(ET + 255) / 256, 256>>>(ei);

    // join: aggregation needs both CSR and gemm1
    cudaEventRecord(evJoin, s1);
    cudaStreamWaitEvent(0, evJoin, 0);

    agg1_k   <<<(NN + 7) / 8, 256>>>(b1);
    gemm2_k  <<<(NN + 127) / 128, 128>>>(W2, as2, ad2);
    agg2_k   <<<(NN + 7) / 8, 256>>>(b2, out);
}